// round 7
// baseline (speedup 1.0000x reference)
#include <cuda_runtime.h>
#include <cstddef>

#define NB 1024          // 32*32 nodes per time slice
#define NT 9
#define TN (NT * NB)     // 9216
#define PRE_D 36         // 9 diag blocks * 4 row-chunks of 256
#define PRE_O 32         // 8 offdiag slices * 4 chunks
#define PRE_CTAS 68

// Compact band scratch.
// g_D[i][p][slot25]: diag value at delta = ey*32+ex, slot=(ey+2)*5+(ex+2)
// g_O[t][p][j9]:     offdiag value at delta with j = (dy+1)*3+(dx+1)
__device__ float g_D[9 * NB * 25];
__device__ float g_O[8 * NB * 9];
__device__ int   g_done;            // pre-CTA completion counter (reset per launch)

// ---------------------------------------------------------------------------
// Per-node 9-point stencil coefficients of A at time slice ts.
// j = (dy+1)*3 + (dx+1); Dirichlet-invalid moves = exact 0.
// ---------------------------------------------------------------------------
__device__ __forceinline__ void coef9(const float* __restrict__ kappa,
                                      const float* __restrict__ m,
                                      const float* __restrict__ H,
                                      int n, int ts, float* c) {
    float kap = kappa[n * NT + ts];
    float k2  = kap * kap;
    float m1  = m[(0 * NB + n) * NT + ts];
    float m2  = m[(1 * NB + n) * NT + ts];
    float H11 = H[(0 * NB + n) * NT + ts];
    float H12 = H[(1 * NB + n) * NT + ts];
    float H22 = H[(3 * NB + n) * NT + ts];

    int ix = n & 31, iy = n >> 5;
    bool xm = ix > 0, xp = ix < 31, ym = iy > 0, yp = iy < 31;

    c[4] = k2 + 2.0f * H11 + 2.0f * H22;
    c[5] = xp         ? ( 0.5f * m1 - H11) : 0.0f;
    c[3] = xm         ? (-0.5f * m1 - H11) : 0.0f;
    c[7] = yp         ? ( 0.5f * m2 - H22) : 0.0f;
    c[1] = ym         ? (-0.5f * m2 - H22) : 0.0f;
    c[8] = (xp && yp) ? (-0.5f * H12)      : 0.0f;
    c[2] = (xp && ym) ? ( 0.5f * H12)      : 0.0f;
    c[6] = (xm && yp) ? ( 0.5f * H12)      : 0.0f;
    c[0] = (xm && ym) ? (-0.5f * H12)      : 0.0f;
}

// Band lookups against a staged table (smem).
__device__ __forceinline__ float dgs(const float* __restrict__ Dp, int d) {
    if (d < -66 || d > 66) return 0.0f;
    int ey = ((d + 68) >> 5) - 2;
    int ex = d - (ey << 5);
    if (ex < -2 || ex > 2) return 0.0f;
    return Dp[(ey + 2) * 5 + ex + 2];
}
__device__ __forceinline__ float ods(const float* __restrict__ Op, int d) {
    unsigned de = (unsigned)(d + 33);
    if (de > 66u) return 0.0f;
    unsigned rr = de & 31u;
    if (rr > 2u) return 0.0f;
    return Op[(de >> 5) * 3 + rr];
}

// ---------------------------------------------------------------------------
// Single fused kernel.
//   CTAs 0..67:      precompute compact band scratch, then signal g_done.
//   CTAs 68..9283:   one output row each: stream 6 zero blocks, wait for
//                    g_done==68, stage this row's 43 band values to smem,
//                    stream the 3 band blocks. Every output byte written once.
// ---------------------------------------------------------------------------
__global__ __launch_bounds__(256, 6)
void k_all(const float* __restrict__ kappa,
           const float* __restrict__ m,
           const float* __restrict__ H,
           float* __restrict__ out) {
    int cb  = blockIdx.x;
    int tid = threadIdx.x;

    __shared__ float sb[388 * 9];       // pre: coef window; row: first 48 floats

    if (cb < PRE_CTAS) {
        // ================= producer CTAs =================
        if (cb < PRE_D) {
            // ---- diag block i, rows p0..p0+255 ----
            int i = cb >> 2, chunk = cb & 3, p0 = chunk << 8;
            int t = (i == 0) ? 0 : i - 1;
            int base = max(0, p0 - 66);
            int hi   = min(NB, p0 + 256 + 66);
            int cnt  = hi - base;

            for (int idx = tid; idx < cnt; idx += 256) {
                float c[9];
                coef9(kappa, m, H, base + idx, t + 1, c);
                if (i > 0) c[4] += 1.0f;        // B = I + A for i>=1
#pragma unroll
                for (int j = 0; j < 9; j++) sb[idx * 9 + j] = c[j];
            }
            __syncthreads();

            int p = p0 + tid;
            float aR[25], aC[25];
#pragma unroll
            for (int k = 0; k < 25; k++) { aR[k] = 0.0f; aC[k] = 0.0f; }

            if (i == 0) {
#pragma unroll
                for (int j1 = 0; j1 < 9; j1++) {
                    int dy1 = j1 / 3 - 1, dx1 = j1 % 3 - 1;
                    int r = p + dy1 * 32 + dx1;
                    if (r < 0 || r >= NB) continue;
                    const float* br = sb + (r - base) * 9;
                    float arp = br[8 - j1];
#pragma unroll
                    for (int j2 = 0; j2 < 9; j2++) {
                        int dy2 = j2 / 3 - 1, dx2 = j2 % 3 - 1;
                        aR[(dy1 + dy2 + 2) * 5 + dx1 + dx2 + 2] += arp * br[j2];
                    }
                }
            } else {
                const float* bp = sb + (p - base) * 9;
#pragma unroll
                for (int j1 = 0; j1 < 9; j1++) {
                    int dy1 = j1 / 3 - 1, dx1 = j1 % 3 - 1;
                    int r = p + dy1 * 32 + dx1;
                    if (r < 0 || r >= NB) continue;
                    float bpr = bp[j1];
                    const float* br = sb + (r - base) * 9;
#pragma unroll
                    for (int j2 = 0; j2 < 9; j2++) {
                        int dy2 = j2 / 3 - 1, dx2 = j2 % 3 - 1;
                        aR[(dy1 + dy2 + 2) * 5 + dx1 + dx2 + 2] += bpr * br[j2];
                    }
                }
#pragma unroll
                for (int js = 0; js < 9; js++) {
                    int dys = js / 3 - 1, dxs = js % 3 - 1;
                    int s = p + dys * 32 + dxs;
                    if (s < 0 || s >= NB) continue;
                    float bsp = sb[(s - base) * 9 + (8 - js)];
#pragma unroll
                    for (int jx = 0; jx < 9; jx++) {
                        int dyx = jx / 3 - 1, dxx = jx % 3 - 1;
                        int x = s - (dyx * 32 + dxx);
                        if (x < 0 || x >= NB) continue;
                        aC[(dys - dyx + 2) * 5 + (dxs - dxx + 2)] +=
                            sb[(x - base) * 9 + jx] * bsp;
                    }
                }
            }

            float* dst = g_D + ((size_t)i * NB + p) * 25;
            float dadd = (i < 8) ? 1.05f : 0.05f;
#pragma unroll
            for (int slot = 0; slot < 25; slot++) {
                float v = (i == 0) ? aR[slot] : 0.5f * (aR[slot] + aC[slot]);
                if (slot == 12) v += dadd;
                dst[slot] = v;
            }
        } else {
            // ---- offdiag slice t, rows p0..p0+255 ----
            int cb2 = cb - PRE_D;
            int t = cb2 >> 2, chunk = cb2 & 3, p0 = chunk << 8;
            int base = max(0, p0 - 33);
            int hi   = min(NB, p0 + 256 + 33);
            int cnt  = hi - base;

            for (int idx = tid; idx < cnt; idx += 256) {
                float c[9];
                coef9(kappa, m, H, base + idx, t + 1, c);
#pragma unroll
                for (int j = 0; j < 9; j++) sb[idx * 9 + j] = c[j];
            }
            __syncthreads();

            int p = p0 + tid;
            const float* ap = sb + (p - base) * 9;
            float* dst = g_O + ((size_t)t * NB + p) * 9;
#pragma unroll
            for (int j = 0; j < 9; j++) {
                int dy = j / 3 - 1, dx = j % 3 - 1;
                int q = p + dy * 32 + dx;
                float v = 0.0f;
                if (q >= 0 && q < NB) {
                    float add = (j == 4) ? 2.0f : 0.0f;   // both invM get +I
                    v = -0.5f * (ap[j] + sb[(q - base) * 9 + (8 - j)] + add);
                }
                dst[j] = v;
            }
        }
        __syncthreads();
        if (tid == 0) {
            __threadfence();
            atomicAdd(&g_done, 1);
        }
        return;
    }

    // ================= row CTAs =================
    int r = cb - PRE_CTAS;              // output row 0..9215
    int i = r >> 10;
    int p = r & (NB - 1);
    float4* rowp = (float4*)(out + (size_t)r * TN);
    float4 z = make_float4(0.f, 0.f, 0.f, 0.f);

    // 1) stream the non-band column blocks (stores drain while we wait)
#pragma unroll
    for (int j = 0; j < 9; j++) {
        if (j < i - 1 || j > i + 1)
            __stcs(rowp + j * 256 + tid, z);
    }

    // 2) wait for producers (resident in wave 1 by construction)
    if (tid == 0) {
        while (atomicAdd(&g_done, 0) < PRE_CTAS) __nanosleep(64);
    }
    __syncthreads();

    // 3) stage this row's band values into smem
    float* sD  = sb;        // 25
    float* sOL = sb + 25;   // 9
    float* sOR = sb + 34;   // 9
    if (tid < 25) {
        sD[tid] = g_D[((size_t)i * NB + p) * 25 + tid];
    } else if (tid >= 32 && tid < 41) {
        if (i > 0) sOL[tid - 32] = g_O[((size_t)(i - 1) * NB + p) * 9 + tid - 32];
    } else if (tid >= 64 && tid < 73) {
        if (i < 8) sOR[tid - 64] = g_O[((size_t)i * NB + p) * 9 + tid - 64];
    }
    __syncthreads();

    // 4) stream the band column blocks
    int q0 = tid << 2;
    int d0 = q0 - p;

    {   // diag block i
        float4 v = z;
        if (d0 + 3 >= -66 && d0 <= 66) {
            v.x = dgs(sD, d0);
            v.y = dgs(sD, d0 + 1);
            v.z = dgs(sD, d0 + 2);
            v.w = dgs(sD, d0 + 3);
        }
        __stcs(rowp + i * 256 + tid, v);
    }
    if (i > 0) {
        float4 v = z;
        if (d0 + 3 >= -33 && d0 <= 33) {
            v.x = ods(sOL, d0);
            v.y = ods(sOL, d0 + 1);
            v.z = ods(sOL, d0 + 2);
            v.w = ods(sOL, d0 + 3);
        }
        __stcs(rowp + (i - 1) * 256 + tid, v);
    }
    if (i < 8) {
        float4 v = z;
        if (d0 + 3 >= -33 && d0 <= 33) {
            v.x = ods(sOR, d0);
            v.y = ods(sOR, d0 + 1);
            v.z = ods(sOR, d0 + 2);
            v.w = ods(sOR, d0 + 3);
        }
        __stcs(rowp + (i + 1) * 256 + tid, v);
    }
}

// ---------------------------------------------------------------------------
// Launcher. Inputs: kappa, m, H, tau (unused). Output: fp32 [1, 9216, 9216].
// ---------------------------------------------------------------------------
extern "C" void kernel_launch(void* const* d_in, const int* in_sizes, int n_in,
                              void* d_out, int out_size) {
    const float* kappa = (const float*)d_in[0];
    const float* m     = (const float*)d_in[1];
    const float* H     = (const float*)d_in[2];
    float* out = (float*)d_out;

    // reset producer counter (tiny memset node; required for graph replays)
    void* done_ptr = nullptr;
    cudaGetSymbolAddress(&done_ptr, g_done);
    cudaMemsetAsync(done_ptr, 0, sizeof(int), 0);

    k_all<<<PRE_CTAS + TN, 256>>>(kappa, m, H, out);
}

// round 8
// speedup vs baseline: 1.0720x; 1.0720x over previous
#include <cuda_runtime.h>
#include <cstddef>

#define NB 1024          // 32*32 nodes per time slice
#define NT 9
#define TN (NT * NB)     // 9216
#define WMAX 135         // coef window nodes (<= 67+68)

// ---------------------------------------------------------------------------
// Per-node 9-point stencil coefficients of A at time slice ts.
// j = (dy+1)*3 + (dx+1); Dirichlet-invalid moves = exact 0.
// ---------------------------------------------------------------------------
__device__ __forceinline__ void coef9(const float* __restrict__ kappa,
                                      const float* __restrict__ m,
                                      const float* __restrict__ H,
                                      int n, int ts, float* c) {
    float kap = kappa[n * NT + ts];
    float k2  = kap * kap;
    float m1  = m[(0 * NB + n) * NT + ts];
    float m2  = m[(1 * NB + n) * NT + ts];
    float H11 = H[(0 * NB + n) * NT + ts];
    float H12 = H[(1 * NB + n) * NT + ts];
    float H22 = H[(3 * NB + n) * NT + ts];

    int ix = n & 31, iy = n >> 5;
    bool xm = ix > 0, xp = ix < 31, ym = iy > 0, yp = iy < 31;

    c[4] = k2 + 2.0f * H11 + 2.0f * H22;
    c[5] = xp         ? ( 0.5f * m1 - H11) : 0.0f;
    c[3] = xm         ? (-0.5f * m1 - H11) : 0.0f;
    c[7] = yp         ? ( 0.5f * m2 - H22) : 0.0f;
    c[1] = ym         ? (-0.5f * m2 - H22) : 0.0f;
    c[8] = (xp && yp) ? (-0.5f * H12)      : 0.0f;
    c[2] = (xp && ym) ? ( 0.5f * H12)      : 0.0f;
    c[6] = (xm && yp) ? ( 0.5f * H12)      : 0.0f;
    c[0] = (xm && ym) ? (-0.5f * H12)      : 0.0f;
}

// Band-slot lookups against the per-row staged table (smem).
__device__ __forceinline__ float dgs(const float* __restrict__ Dp, int d) {
    if (d < -66 || d > 66) return 0.0f;
    int ey = ((d + 68) >> 5) - 2;
    int ex = d - (ey << 5);
    if (ex < -2 || ex > 2) return 0.0f;
    return Dp[(ey + 2) * 5 + ex + 2];
}
__device__ __forceinline__ float ods(const float* __restrict__ Op, int d) {
    unsigned de = (unsigned)(d + 33);
    if (de > 66u) return 0.0f;
    unsigned rr = de & 31u;
    if (rr > 2u) return 0.0f;
    return Op[(de >> 5) * 3 + rr];
}

// ---------------------------------------------------------------------------
// Single self-contained kernel: one CTA per output row.
//   1) stream 6 non-band column blocks (zeros)
//   2) stage plain-A coefficient window (<=2 slices) into smem
//   3) 43 threads compute this row's band values (2 scalar accumulators each)
//   4) stream 3 band column blocks from smem
// Every output byte written exactly once; no global scratch, no inter-CTA dep.
// ---------------------------------------------------------------------------
__global__ __launch_bounds__(256)
void k_all(const float* __restrict__ kappa,
           const float* __restrict__ m,
           const float* __restrict__ H,
           float* __restrict__ out) {
    int r   = blockIdx.x;               // output row 0..9215
    int i   = r >> 10;                  // block row
    int p   = r & (NB - 1);
    int tid = threadIdx.x;
    float4* rowp = (float4*)(out + (size_t)r * TN);
    float4 z = make_float4(0.f, 0.f, 0.f, 0.f);

    // ---- 1) zero blocks first: stores drain while we do band math ----
#pragma unroll
    for (int j = 0; j < 9; j++) {
        if (j < i - 1 || j > i + 1)
            __stcs(rowp + j * 256 + tid, z);
    }

    // ---- 2) stage coefficient window (plain A) ----
    // slices: t0 = diag + left offdiag, t1 = right offdiag (i in 1..7)
    int t0  = (i == 0) ? 0 : (i - 1);
    int nsl = (i >= 1 && i <= 7) ? 2 : 1;
    int base = max(0, p - 67);
    int hiw  = min(NB, p + 68);
    int cnt  = hiw - base;

    __shared__ float sA0[WMAX * 9];
    __shared__ float sA1[WMAX * 9];
    __shared__ float sBand[48];         // [0..24] diag, [25..33] L, [34..42] R

    for (int idx = tid; idx < cnt * nsl; idx += 256) {
        int sl  = (idx >= cnt) ? 1 : 0;
        int loc = idx - sl * cnt;
        float c[9];
        coef9(kappa, m, H, base + loc, (sl ? i : t0) + 1, c);
        float* dst = (sl ? sA1 : sA0) + loc * 9;
#pragma unroll
        for (int j = 0; j < 9; j++) dst[j] = c[j];
    }
    __syncthreads();

    // ---- 3) band slot computation ----
    if (tid < 25) {
        // diag slot: delta = ey*32 + ex
        int ey = tid / 5 - 2, ex = tid % 5 - 2;
        int delta = ey * 32 + ex;
        int q = p + delta;
        float v = 0.0f;
        if (q >= 0 && q < NB) {
            if (i == 0) {
                // (A^T A)[p][q] = sum_r A[r][p] * A[r][q]
                float acc = 0.0f;
#pragma unroll
                for (int j = 0; j < 9; j++) {
                    int dy = j / 3 - 1, dx = j % 3 - 1;
                    int rr = p + dy * 32 + dx;
                    if (rr < 0 || rr >= NB) continue;
                    int ddy = ey - dy, ddx = ex - dx;
                    if (ddy < -1 || ddy > 1 || ddx < -1 || ddx > 1) continue;
                    int j2 = (ddy + 1) * 3 + (ddx + 1);
                    acc += sA0[(rr - base) * 9 + (8 - j)] *
                           sA0[(rr - base) * 9 + j2];
                }
                v = acc + ((delta == 0) ? 1.05f : 0.0f);
            } else {
                // 0.5*(MM + MM^T)[p][q],  MM = (I+A)^2, slice t0
                float mmpq = 0.0f, mmqp = 0.0f;
#pragma unroll
                for (int j = 0; j < 9; j++) {
                    int dy = j / 3 - 1, dx = j % 3 - 1;
                    {   // MM[p][q]: p -> rr -> q
                        int rr = p + dy * 32 + dx;
                        int ddy = ey - dy, ddx = ex - dx;
                        if (rr >= 0 && rr < NB &&
                            ddy >= -1 && ddy <= 1 && ddx >= -1 && ddx <= 1) {
                            int j2 = (ddy + 1) * 3 + (ddx + 1);
                            float a = sA0[(p - base) * 9 + j]   + ((j  == 4) ? 1.0f : 0.0f);
                            float b = sA0[(rr - base) * 9 + j2] + ((j2 == 4) ? 1.0f : 0.0f);
                            mmpq += a * b;
                        }
                    }
                    {   // MM[q][p]: q -> ss -> p
                        int ss = q + dy * 32 + dx;
                        int ddy = -ey - dy, ddx = -ex - dx;
                        if (ss >= 0 && ss < NB &&
                            ddy >= -1 && ddy <= 1 && ddx >= -1 && ddx <= 1) {
                            int j2 = (ddy + 1) * 3 + (ddx + 1);
                            float a = sA0[(q - base) * 9 + j]   + ((j  == 4) ? 1.0f : 0.0f);
                            float b = sA0[(ss - base) * 9 + j2] + ((j2 == 4) ? 1.0f : 0.0f);
                            mmqp += a * b;
                        }
                    }
                }
                v = 0.5f * (mmpq + mmqp) +
                    ((delta == 0) ? ((i < 8) ? 1.05f : 0.05f) : 0.0f);
            }
        }
        sBand[tid] = v;
    } else if (tid >= 32 && tid < 41) {
        // left offdiag block (slice i-1 = t0): -0.5*(B + B^T)[p][q]
        int j = tid - 32;
        float v = 0.0f;
        if (i > 0) {
            int dy = j / 3 - 1, dx = j % 3 - 1;
            int q = p + dy * 32 + dx;
            if (q >= 0 && q < NB) {
                float add = (j == 4) ? 2.0f : 0.0f;
                v = -0.5f * (sA0[(p - base) * 9 + j] +
                             sA0[(q - base) * 9 + (8 - j)] + add);
            }
        }
        sBand[25 + j] = v;
    } else if (tid >= 64 && tid < 73) {
        // right offdiag block (slice i): table sA1 for 1<=i<=7, sA0 for i=0
        int j = tid - 64;
        float v = 0.0f;
        if (i < 8) {
            const float* sR = (i == 0) ? sA0 : sA1;
            int dy = j / 3 - 1, dx = j % 3 - 1;
            int q = p + dy * 32 + dx;
            if (q >= 0 && q < NB) {
                float add = (j == 4) ? 2.0f : 0.0f;
                v = -0.5f * (sR[(p - base) * 9 + j] +
                             sR[(q - base) * 9 + (8 - j)] + add);
            }
        }
        sBand[34 + j] = v;
    }
    __syncthreads();

    // ---- 4) band blocks ----
    int q0 = tid << 2;
    int d0 = q0 - p;

    {   // diag block i
        float4 v = z;
        if (d0 + 3 >= -66 && d0 <= 66) {
            v.x = dgs(sBand, d0);
            v.y = dgs(sBand, d0 + 1);
            v.z = dgs(sBand, d0 + 2);
            v.w = dgs(sBand, d0 + 3);
        }
        __stcs(rowp + i * 256 + tid, v);
    }
    if (i > 0) {
        float4 v = z;
        if (d0 + 3 >= -33 && d0 <= 33) {
            v.x = ods(sBand + 25, d0);
            v.y = ods(sBand + 25, d0 + 1);
            v.z = ods(sBand + 25, d0 + 2);
            v.w = ods(sBand + 25, d0 + 3);
        }
        __stcs(rowp + (i - 1) * 256 + tid, v);
    }
    if (i < 8) {
        float4 v = z;
        if (d0 + 3 >= -33 && d0 <= 33) {
            v.x = ods(sBand + 34, d0);
            v.y = ods(sBand + 34, d0 + 1);
            v.z = ods(sBand + 34, d0 + 2);
            v.w = ods(sBand + 34, d0 + 3);
        }
        __stcs(rowp + (i + 1) * 256 + tid, v);
    }
}

// ---------------------------------------------------------------------------
// Launcher. Inputs: kappa, m, H, tau (unused). Output: fp32 [1, 9216, 9216].
// ---------------------------------------------------------------------------
extern "C" void kernel_launch(void* const* d_in, const int* in_sizes, int n_in,
                              void* d_out, int out_size) {
    const float* kappa = (const float*)d_in[0];
    const float* m     = (const float*)d_in[1];
    const float* H     = (const float*)d_in[2];
    float* out = (float*)d_out;

    k_all<<<TN, 256>>>(kappa, m, H, out);
}